// round 1
// baseline (speedup 1.0000x reference)
#include <cuda_runtime.h>
#include <math_constants.h>

#define NUM_EMB 1024
#define EMB_DIM 256
#define NROWS   65536
#define NQ      (NROWS * EMB_DIM)

// ---------------- device-global scratch (no allocations allowed) ----------------
__device__ float g_ET[NUM_EMB * EMB_DIM];   // E^T [k][d], 1 MB
__device__ float g_e2[NUM_EMB];             // ||e_k||^2
__device__ int   g_counts[NUM_EMB];         // codebook usage histogram
__device__ float g_sse;                     // sum (q - z)^2

// ---------------- helpers: packed fp32x2 ----------------
__device__ __forceinline__ unsigned long long pk2(float x, float y) {
    unsigned long long r;
    asm("mov.b64 %0, {%1,%2};" : "=l"(r) : "f"(x), "f"(y));
    return r;
}
__device__ __forceinline__ void upk2(unsigned long long v, float& x, float& y) {
    asm("mov.b64 {%0,%1}, %2;" : "=f"(x), "=f"(y) : "l"(v));
}
#define FFMA2(acc, a, b) \
    asm("fma.rn.f32x2 %0, %1, %2, %0;" : "+l"(acc) : "l"(a), "l"(b))

// ---------------- kernels ----------------
__global__ void vq_zero() {
    int t = blockIdx.x * blockDim.x + threadIdx.x;
    if (t < NUM_EMB) g_counts[t] = 0;
    if (t == 0) g_sse = 0.0f;
}

// E [256][1024] -> g_ET [1024][256]
__global__ void vq_transpose(const float* __restrict__ E) {
    __shared__ float tile[32][33];
    int x = blockIdx.x * 32;   // k base
    int y = blockIdx.y * 32;   // d base
    int tx = threadIdx.x, ty = threadIdx.y;  // (32, 8)
#pragma unroll
    for (int i = 0; i < 32; i += 8)
        tile[ty + i][tx] = E[(y + ty + i) * NUM_EMB + x + tx];
    __syncthreads();
#pragma unroll
    for (int i = 0; i < 32; i += 8)
        g_ET[(x + ty + i) * EMB_DIM + y + tx] = tile[tx][ty + i];
}

__global__ void vq_e2(const float* __restrict__ E) {
    int k = blockIdx.x * blockDim.x + threadIdx.x;  // 0..1023
    float s0 = 0.f, s1 = 0.f, s2 = 0.f, s3 = 0.f;
    for (int d = 0; d < EMB_DIM; d += 4) {
        float a = E[(d + 0) * NUM_EMB + k];
        float b = E[(d + 1) * NUM_EMB + k];
        float c = E[(d + 2) * NUM_EMB + k];
        float e = E[(d + 3) * NUM_EMB + k];
        s0 = fmaf(a, a, s0); s1 = fmaf(b, b, s1);
        s2 = fmaf(c, c, s2); s3 = fmaf(e, e, s3);
    }
    g_e2[k] = (s0 + s1) + (s2 + s3);
}

// SMEM layout (floats):
//   zt  : 256*68  (z tile transposed [d][row], padded)
//   et  : 32*128  (E chunk [dd][code])
//   z2s : 64
//   rd  : 64*16   (per-row per-codegroup best dist; reused for sse reduce)
//   rk  : 64*16   (ints)
//   bkA : 64      (ints)
#define SM_ZT   (256 * 68)
#define SM_ET   (32 * 128)
#define SM_FLOATS (SM_ZT + SM_ET + 64 + 1024 + 1024 + 64)
#define SMEM_BYTES (SM_FLOATS * 4)

__global__ __launch_bounds__(256, 2)
void vq_main(const float* __restrict__ z, const float* __restrict__ E,
             float* __restrict__ out, int writeIdx) {
    extern __shared__ float sm[];
    float* zt  = sm;
    float* et  = zt + SM_ZT;
    float* z2s = et + SM_ET;
    float* rd  = z2s + 64;
    int*   rkk = (int*)(rd + 1024);
    int*   bkA = rkk + 1024;

    const int t = threadIdx.x;
    const int base = blockIdx.x * 64;     // first row of this block
    const float4* z4 = (const float4*)z;

    // ---- load z tile, transposed into smem ----
#pragma unroll
    for (int i = 0; i < 16; i++) {
        int gi = i * 256 + t;             // 4096 float4s
        int r = gi >> 6, d4 = gi & 63;
        float4 v = z4[(base + r) * 64 + d4];
        int db = d4 * 4;
        zt[(db + 0) * 68 + r] = v.x;
        zt[(db + 1) * 68 + r] = v.y;
        zt[(db + 2) * 68 + r] = v.z;
        zt[(db + 3) * 68 + r] = v.w;
    }
    __syncthreads();

    // ---- per-row ||z||^2 ----
    if (t < 64) {
        float s0 = 0.f, s1 = 0.f, s2 = 0.f, s3 = 0.f;
        for (int d = 0; d < 256; d += 4) {
            float a = zt[(d + 0) * 68 + t];
            float b = zt[(d + 1) * 68 + t];
            float c = zt[(d + 2) * 68 + t];
            float e = zt[(d + 3) * 68 + t];
            s0 = fmaf(a, a, s0); s1 = fmaf(b, b, s1);
            s2 = fmaf(c, c, s2); s3 = fmaf(e, e, s3);
        }
        z2s[t] = (s0 + s1) + (s2 + s3);
    }
    __syncthreads();

    const int tr = t >> 4;   // row group: rows tr*4 .. tr*4+3
    const int tc = t & 15;   // code group: codes tc*8 .. tc*8+7 (within tile)

    float myz2[4];
#pragma unroll
    for (int r = 0; r < 4; r++) myz2[r] = z2s[tr * 4 + r];

    float bd[4]; int bk[4];
#pragma unroll
    for (int r = 0; r < 4; r++) { bd[r] = CUDART_INF_F; bk[r] = 0; }

    // ---- main GEMM-argmin: 8 code tiles of 128, 8 d-chunks of 32 ----
    for (int kt = 0; kt < 8; ++kt) {
        unsigned long long acc[4][4];
#pragma unroll
        for (int r = 0; r < 4; r++)
#pragma unroll
            for (int p = 0; p < 4; p++) acc[r][p] = 0ULL;

        for (int dc = 0; dc < 8; ++dc) {
            __syncthreads();
#pragma unroll
            for (int i = 0; i < 16; i++) {
                int li = i * 256 + t;     // 4096 floats
                int dd = li >> 7, kk = li & 127;
                et[dd * 128 + kk] = E[(dc * 32 + dd) * NUM_EMB + kt * 128 + kk];
            }
            __syncthreads();
#pragma unroll
            for (int dd = 0; dd < 32; ++dd) {
                const float4 zv = *(const float4*)&zt[(dc * 32 + dd) * 68 + tr * 4];
                unsigned long long zz0 = pk2(zv.x, zv.x);
                unsigned long long zz1 = pk2(zv.y, zv.y);
                unsigned long long zz2 = pk2(zv.z, zv.z);
                unsigned long long zz3 = pk2(zv.w, zv.w);
                const ulonglong2 ea = *(const ulonglong2*)&et[dd * 128 + tc * 8];
                const ulonglong2 eb = *(const ulonglong2*)&et[dd * 128 + tc * 8 + 4];
                FFMA2(acc[0][0], zz0, ea.x); FFMA2(acc[0][1], zz0, ea.y);
                FFMA2(acc[0][2], zz0, eb.x); FFMA2(acc[0][3], zz0, eb.y);
                FFMA2(acc[1][0], zz1, ea.x); FFMA2(acc[1][1], zz1, ea.y);
                FFMA2(acc[1][2], zz1, eb.x); FFMA2(acc[1][3], zz1, eb.y);
                FFMA2(acc[2][0], zz2, ea.x); FFMA2(acc[2][1], zz2, ea.y);
                FFMA2(acc[2][2], zz2, eb.x); FFMA2(acc[2][3], zz2, eb.y);
                FFMA2(acc[3][0], zz3, ea.x); FFMA2(acc[3][1], zz3, ea.y);
                FFMA2(acc[3][2], zz3, eb.x); FFMA2(acc[3][3], zz3, eb.y);
            }
        }

        // ---- distances + running argmin (ascending k; strict < => first-min) ----
#pragma unroll
        for (int p = 0; p < 4; p++) {
            int k = kt * 128 + tc * 8 + p * 2;
            float e2a = g_e2[k], e2b = g_e2[k + 1];
#pragma unroll
            for (int r = 0; r < 4; r++) {
                float lo, hi;
                upk2(acc[r][p], lo, hi);
                // match reference fp32 rounding: round(z2 + e2) - round(2*dot)
                float dl = __fadd_rn(__fadd_rn(myz2[r], e2a), -2.0f * lo);
                if (dl < bd[r]) { bd[r] = dl; bk[r] = k; }
                float dh = __fadd_rn(__fadd_rn(myz2[r], e2b), -2.0f * hi);
                if (dh < bd[r]) { bd[r] = dh; bk[r] = k + 1; }
            }
        }
    }

    // ---- cross-thread argmin reduce (16 code-groups per row) ----
#pragma unroll
    for (int r = 0; r < 4; r++) {
        int row = tr * 4 + r;
        rd[row * 16 + tc]  = bd[r];
        rkk[row * 16 + tc] = bk[r];
    }
    __syncthreads();
    if (t < 64) {
        float b = rd[t * 16]; int k = rkk[t * 16];
#pragma unroll
        for (int i = 1; i < 16; i++) {
            float d = rd[t * 16 + i]; int kk = rkk[t * 16 + i];
            if (d < b || (d == b && kk < k)) { b = d; k = kk; }
        }
        bkA[t] = k;
        atomicAdd(&g_counts[k], 1);
        if (writeIdx) out[NQ + base + t] = (float)k;
    }
    __syncthreads();

    // ---- epilogue: gather quantized (from E^T), straight-through out, sse ----
    {
        const int row = t >> 2, q = t & 3;
        const int k = bkA[row];
        const float4* ET4 = (const float4*)g_ET;
        float4* out4 = (float4*)out;
        float s = 0.0f;
#pragma unroll
        for (int j = 0; j < 16; j++) {
            int ei = (k << 6) + (q << 4) + j;
            float4 ev = ET4[ei];
            int zi = ((base + row) << 6) + (q << 4) + j;
            float4 zv = z4[zi];
            float dx = __fadd_rn(ev.x, -zv.x);
            float dy = __fadd_rn(ev.y, -zv.y);
            float dz = __fadd_rn(ev.z, -zv.z);
            float dw = __fadd_rn(ev.w, -zv.w);
            float4 o;
            o.x = __fadd_rn(zv.x, dx);
            o.y = __fadd_rn(zv.y, dy);
            o.z = __fadd_rn(zv.z, dz);
            o.w = __fadd_rn(zv.w, dw);
            out4[zi] = o;
            s = fmaf(dx, dx, s); s = fmaf(dy, dy, s);
            s = fmaf(dz, dz, s); s = fmaf(dw, dw, s);
        }
        rd[t] = s;
        __syncthreads();
        for (int st = 128; st > 0; st >>= 1) {
            if (t < st) rd[t] += rd[t + st];
            __syncthreads();
        }
        if (t == 0) atomicAdd(&g_sse, rd[0]);
    }
}

__global__ void vq_final(float* __restrict__ out, int out_size) {
    __shared__ float sb[1024];
    int t = threadIdx.x;
    float avg = (float)g_counts[t] * (1.0f / 65536.0f);
    sb[t] = avg * logf(avg + 1e-10f);
    __syncthreads();
    for (int s = 512; s > 0; s >>= 1) {
        if (t < s) sb[t] += sb[t + s];
        __syncthreads();
    }
    if (t == 0 && out_size >= NQ + NROWS + 3) {
        float vq = g_sse * (1.0f / 16777216.0f);
        out[NQ + NROWS + 0] = vq;
        out[NQ + NROWS + 1] = 0.25f * vq;    // beta * same mean
        out[NQ + NROWS + 2] = expf(-sb[0]);  // perplexity
    }
}

// ---------------- launch ----------------
extern "C" void kernel_launch(void* const* d_in, const int* in_sizes, int n_in,
                              void* d_out, int out_size) {
    const float* z = (const float*)d_in[0];
    const float* E = (const float*)d_in[1];
    // robustness: metadata order should be (z, embeddings); swap if sizes say otherwise
    if (n_in >= 2 && in_sizes[0] == NUM_EMB * EMB_DIM && in_sizes[1] == NQ) {
        const float* tmp = z; z = E; E = tmp;
    }
    float* out = (float*)d_out;
    int writeIdx = (out_size >= NQ + NROWS) ? 1 : 0;

    cudaFuncSetAttribute(vq_main, cudaFuncAttributeMaxDynamicSharedMemorySize, SMEM_BYTES);

    vq_zero<<<4, 256>>>();
    vq_transpose<<<dim3(32, 8), dim3(32, 8)>>>(E);
    vq_e2<<<4, 256>>>(E);
    vq_main<<<1024, 256, SMEM_BYTES>>>(z, E, out, writeIdx);
    if (out_size >= NQ + NROWS + 3)
        vq_final<<<1, 1024>>>(out, out_size);
}

// round 2
// speedup vs baseline: 1.4057x; 1.4057x over previous
#include <cuda_runtime.h>
#include <math_constants.h>

#define NUM_EMB 1024
#define EMB_DIM 256
#define NROWS   65536
#define NQ      (NROWS * EMB_DIM)

// ---------------- device-global scratch ----------------
__device__ float g_ET[NUM_EMB * EMB_DIM];   // E^T [k][d]
__device__ float g_e2[NUM_EMB];             // ||e_k||^2
__device__ int   g_counts[NUM_EMB];
__device__ float g_sse;

// ---------------- packed fp32x2 helpers ----------------
__device__ __forceinline__ unsigned long long pk2(float x, float y) {
    unsigned long long r;
    asm("mov.b64 %0, {%1,%2};" : "=l"(r) : "f"(x), "f"(y));
    return r;
}
__device__ __forceinline__ void upk2(unsigned long long v, float& x, float& y) {
    asm("mov.b64 {%0,%1}, %2;" : "=f"(x), "=f"(y) : "l"(v));
}
#define FFMA2(acc, a, b) \
    asm("fma.rn.f32x2 %0, %1, %2, %0;" : "+l"(acc) : "l"(a), "l"(b))

// ---------------- small kernels ----------------
__global__ void vq_zero() {
    int t = blockIdx.x * blockDim.x + threadIdx.x;
    if (t < NUM_EMB) g_counts[t] = 0;
    if (t == 0) g_sse = 0.0f;
}

__global__ void vq_transpose(const float* __restrict__ E) {
    __shared__ float tile[32][33];
    int x = blockIdx.x * 32, y = blockIdx.y * 32;
    int tx = threadIdx.x, ty = threadIdx.y;
#pragma unroll
    for (int i = 0; i < 32; i += 8)
        tile[ty + i][tx] = E[(y + ty + i) * NUM_EMB + x + tx];
    __syncthreads();
#pragma unroll
    for (int i = 0; i < 32; i += 8)
        g_ET[(x + ty + i) * EMB_DIM + y + tx] = tile[tx][ty + i];
}

__global__ void vq_e2(const float* __restrict__ E) {
    int k = blockIdx.x * blockDim.x + threadIdx.x;
    float s0 = 0.f, s1 = 0.f, s2 = 0.f, s3 = 0.f;
    for (int d = 0; d < EMB_DIM; d += 4) {
        float a = E[(d + 0) * NUM_EMB + k];
        float b = E[(d + 1) * NUM_EMB + k];
        float c = E[(d + 2) * NUM_EMB + k];
        float e = E[(d + 3) * NUM_EMB + k];
        s0 = fmaf(a, a, s0); s1 = fmaf(b, b, s1);
        s2 = fmaf(c, c, s2); s3 = fmaf(e, e, s3);
    }
    g_e2[k] = (s0 + s1) + (s2 + s3);
}

// ---------------- main kernel ----------------
// Block: 256 threads, tile = 128 rows x all 1024 codes (4 kt-tiles of 256).
// Thread tile: 8 rows x 16 codes (strided: codes tc + 16*j within kt tile).
// SMEM (floats):
//   zs  : 128*256  z tile, NATURAL layout (z reads are warp-broadcast)
//   et  : 32*256   E chunk [dd][k]
//   e2s : 1024
//   rd  : 128*16   (reduce dists; reused for sse)
//   rk  : 128*16   (ints)
//   bkA : 128      (ints)
//   z2s : 128
#define SM_ZS   (128 * 256)
#define SM_ET   (32 * 256)
#define SM_FLOATS (SM_ZS + SM_ET + 1024 + 2048 + 2048 + 128 + 128)
#define SMEM_BYTES (SM_FLOATS * 4)

__global__ __launch_bounds__(256, 1)
void vq_main(const float* __restrict__ z, const float* __restrict__ E,
             float* __restrict__ out, int writeIdx) {
    extern __shared__ float sm[];
    float* zs  = sm;
    float* et  = zs + SM_ZS;
    float* e2s = et + SM_ET;
    float* rd  = e2s + 1024;
    int*   rkk = (int*)(rd + 2048);
    int*   bkA = rkk + 2048;
    float* z2s = (float*)(bkA + 128);

    const int t = threadIdx.x;
    const int base = blockIdx.x * 128;
    const float4* z4 = (const float4*)z;
    const float4* E4 = (const float4*)E;
    float4* zs4 = (float4*)zs;
    float4* et4 = (float4*)et;

    // ---- stage z tile (straight copy, coalesced, conflict-free) ----
#pragma unroll
    for (int i = 0; i < 32; i++)
        zs4[i * 256 + t] = z4[base * 64 + i * 256 + t];
    // ---- stage e2 ----
    ((float4*)e2s)[t] = ((const float4*)g_e2)[t];
    __syncthreads();

    // ---- per-row ||z||^2 (diagonal iteration to dodge bank conflicts) ----
    if (t < 128) {
        float s0 = 0.f, s1 = 0.f, s2 = 0.f, s3 = 0.f;
#pragma unroll 8
        for (int i = 0; i < 64; i++) {
            int j = (i + t) & 63;
            float4 v = zs4[t * 64 + j];
            s0 = fmaf(v.x, v.x, s0); s1 = fmaf(v.y, v.y, s1);
            s2 = fmaf(v.z, v.z, s2); s3 = fmaf(v.w, v.w, s3);
        }
        z2s[t] = (s0 + s1) + (s2 + s3);
    }

    const int tr = t >> 4;   // row group: rows tr*8 .. tr*8+7
    const int tc = t & 15;   // code lane: codes tc + 16*j (j=0..15) in kt tile

    float bd[8]; int bk[8];
#pragma unroll
    for (int r = 0; r < 8; r++) { bd[r] = CUDART_INF_F; bk[r] = 0; }

    const float* zsrowB = zs + tr * 8 * 256;

    for (int kt = 0; kt < 4; ++kt) {
        unsigned long long acc[8][8];
#pragma unroll
        for (int r = 0; r < 8; r++)
#pragma unroll
            for (int p = 0; p < 8; p++) acc[r][p] = 0ULL;

        for (int dc = 0; dc < 8; ++dc) {
            __syncthreads();
            // load E chunk: rows dc*32..+31, cols kt*256..+255 (coalesced)
#pragma unroll
            for (int i = 0; i < 8; i++) {
                int li = i * 256 + t;           // 2048 float4s
                int dd = li >> 6, k4 = li & 63;
                et4[li] = E4[(dc * 32 + dd) * 256 + kt * 64 + k4];
            }
            __syncthreads();

            const float* zsrow = zsrowB + dc * 32;
#pragma unroll 4
            for (int dd = 0; dd < 32; ++dd) {
                // z: 8 rows, warp-broadcast scalar LDS
                unsigned long long zz[8];
#pragma unroll
                for (int r = 0; r < 8; r++) {
                    float zv = zsrow[r * 256 + dd];
                    zz[r] = pk2(zv, zv);
                }
                // e: 16 strided codes -> 8 packed pairs (codes tc+32p, tc+32p+16)
                const float* etd = et + dd * 256 + tc;
                unsigned long long ee[8];
#pragma unroll
                for (int p = 0; p < 8; p++)
                    ee[p] = pk2(etd[p * 32], etd[p * 32 + 16]);
#pragma unroll
                for (int r = 0; r < 8; r++) {
#pragma unroll
                    for (int p = 0; p < 8; p++)
                        FFMA2(acc[r][p], zz[r], ee[p]);
                }
            }
        }

        // ---- distances + running argmin (k ascending within thread) ----
#pragma unroll
        for (int p = 0; p < 8; p++) {
            int kA = kt * 256 + tc + p * 32;   // lo lane
            int kB = kA + 16;                  // hi lane
            float e2a = e2s[kA & 1023];
            float e2b = e2s[kB & 1023];
#pragma unroll
            for (int r = 0; r < 8; r++) {
                float z2 = z2s[tr * 8 + r];
                float lo, hi;
                upk2(acc[r][p], lo, hi);
                float dl = __fadd_rn(__fadd_rn(z2, e2a), -2.0f * lo);
                if (dl < bd[r]) { bd[r] = dl; bk[r] = kA; }
                float dh = __fadd_rn(__fadd_rn(z2, e2b), -2.0f * hi);
                if (dh < bd[r]) { bd[r] = dh; bk[r] = kB; }
            }
        }
    }

    // ---- cross-thread argmin reduce (16 lanes per row) ----
#pragma unroll
    for (int r = 0; r < 8; r++) {
        int row = tr * 8 + r;
        rd[row * 16 + tc]  = bd[r];
        rkk[row * 16 + tc] = bk[r];
    }
    __syncthreads();
    if (t < 128) {
        float b = rd[t * 16]; int k = rkk[t * 16];
#pragma unroll
        for (int i = 1; i < 16; i++) {
            float d = rd[t * 16 + i]; int kk = rkk[t * 16 + i];
            if (d < b || (d == b && kk < k)) { b = d; k = kk; }
        }
        bkA[t] = k;
        atomicAdd(&g_counts[k], 1);
        if (writeIdx) out[NQ + base + t] = (float)k;
    }
    __syncthreads();

    // ---- epilogue: gather quantized (E^T), straight-through out, sse ----
    {
        const int row = t >> 1, h = t & 1;     // 2 threads per row
        const int k = bkA[row];
        const float4* ET4 = (const float4*)g_ET;
        float4* out4 = (float4*)out;
        float s = 0.0f;
#pragma unroll
        for (int j = 0; j < 32; j++) {
            int ei = (k << 6) + (h << 5) + j;
            float4 ev = ET4[ei];
            int zi = ((base + row) << 6) + (h << 5) + j;
            float4 zv = z4[zi];
            float dx = __fadd_rn(ev.x, -zv.x);
            float dy = __fadd_rn(ev.y, -zv.y);
            float dz = __fadd_rn(ev.z, -zv.z);
            float dw = __fadd_rn(ev.w, -zv.w);
            float4 o;
            o.x = __fadd_rn(zv.x, dx);
            o.y = __fadd_rn(zv.y, dy);
            o.z = __fadd_rn(zv.z, dz);
            o.w = __fadd_rn(zv.w, dw);
            out4[zi] = o;
            s = fmaf(dx, dx, s); s = fmaf(dy, dy, s);
            s = fmaf(dz, dz, s); s = fmaf(dw, dw, s);
        }
        rd[t] = s;
        __syncthreads();
        for (int st = 128; st > 0; st >>= 1) {
            if (t < st) rd[t] += rd[t + st];
            __syncthreads();
        }
        if (t == 0) atomicAdd(&g_sse, rd[0]);
    }
}

__global__ void vq_final(float* __restrict__ out, int out_size) {
    __shared__ float sb[1024];
    int t = threadIdx.x;
    float avg = (float)g_counts[t] * (1.0f / 65536.0f);
    sb[t] = avg * logf(avg + 1e-10f);
    __syncthreads();
    for (int s = 512; s > 0; s >>= 1) {
        if (t < s) sb[t] += sb[t + s];
        __syncthreads();
    }
    if (t == 0 && out_size >= NQ + NROWS + 3) {
        float vq = g_sse * (1.0f / 16777216.0f);
        out[NQ + NROWS + 0] = vq;
        out[NQ + NROWS + 1] = 0.25f * vq;
        out[NQ + NROWS + 2] = expf(-sb[0]);
    }
}

// ---------------- launch ----------------
extern "C" void kernel_launch(void* const* d_in, const int* in_sizes, int n_in,
                              void* d_out, int out_size) {
    const float* z = (const float*)d_in[0];
    const float* E = (const float*)d_in[1];
    if (n_in >= 2 && in_sizes[0] == NUM_EMB * EMB_DIM && in_sizes[1] == NQ) {
        const float* tmp = z; z = E; E = tmp;
    }
    float* out = (float*)d_out;
    int writeIdx = (out_size >= NQ + NROWS) ? 1 : 0;

    cudaFuncSetAttribute(vq_main, cudaFuncAttributeMaxDynamicSharedMemorySize, SMEM_BYTES);

    vq_zero<<<4, 256>>>();
    vq_transpose<<<dim3(32, 8), dim3(32, 8)>>>(E);
    vq_e2<<<4, 256>>>(E);
    vq_main<<<512, 256, SMEM_BYTES>>>(z, E, out, writeIdx);
    if (out_size >= NQ + NROWS + 3)
        vq_final<<<1, 1024>>>(out, out_size);
}